// round 1
// baseline (speedup 1.0000x reference)
#include <cuda_runtime.h>
#include <math.h>

// ---------------- problem constants ----------------
#define BATCH  4
#define NH     8
#define NCH    64          // chunks per batch
#define SROWS  4096        // seq rows per batch (seq[:,1:])
#define CROWS  8192        // left-padded ctx rows per batch
#define DMODEL 1024
#define DINNER 512
#define JDIM   129         // 1 null key + 128 ctx keys

// ---------------- scratch (device globals; no allocation) ----------------
__device__ float g_Q [(size_t)BATCH * SROWS * DINNER];          //  33.5 MB (q * 1/8 folded in)
__device__ float g_KV[(size_t)BATCH * CROWS * 1024];            // 134 MB  (cols 0..511 = K, 512..1023 = V)
__device__ float g_P [(size_t)BATCH * NH * NCH * 64 * JDIM];    // 108 MB  softmax(sim)
__device__ float g_Pm[(size_t)BATCH * NH * NCH * 64 * JDIM];    // 108 MB  head-mixed attn
__device__ float g_O [(size_t)BATCH * SROWS * DINNER];          //  33.5 MB attention output

// ---------------- SGEMM: 128x128 tile, 8x8 microtile, BK=8 ----------------
// a_mode: 0 = plain Ap, 1 = seq remap (row -> seq[b, t+1]), 2 = ctx pad remap
//         (first 127 rows of each batch are zero), 3 = read g_O
// c_mode: 0 = write g_Q, 1 = write g_KV, 2 = write Cp with d_out row remap
__global__ __launch_bounds__(256)
void sgemm_kernel(const float* __restrict__ Ap, const float* __restrict__ Bm,
                  float* __restrict__ Cp, int M, int N, int K,
                  float alpha, const float* __restrict__ bias,
                  int a_mode, int c_mode)
{
    __shared__ float As[8][128];
    __shared__ float Bs[8][128];
    const int tid  = threadIdx.x;
    const int bcol = blockIdx.x, brow = blockIdx.y;

    const int irA = tid >> 1, icA = (tid & 1) << 2;
    const int irB = tid >> 5, icB = (tid & 31) << 2;
    const int trow = tid >> 4, tcol = tid & 15;

    const int arow = brow * 128 + irA;
    const float* Arow = nullptr;
    bool a_zero = false;
    if (a_mode == 0) {
        Arow = Ap + (size_t)arow * K;
    } else if (a_mode == 1) {
        int b = arow >> 12, t = arow & 4095;
        Arow = Ap + ((size_t)b * 4097 + t + 1) * K;
    } else if (a_mode == 2) {
        int b = arow >> 13, r = arow & 8191;
        if (r < 127) a_zero = true;
        else         Arow = Ap + ((size_t)b * 8065 + (r - 127)) * K;
    } else {
        Arow = g_O + (size_t)arow * K;
    }

    const float* Bptr = Bm + (size_t)irB * N + bcol * 128 + icB;

    float acc[8][8] = {};

    for (int k0 = 0; k0 < K; k0 += 8) {
        float4 av = a_zero ? make_float4(0.f, 0.f, 0.f, 0.f)
                           : *reinterpret_cast<const float4*>(Arow + k0 + icA);
        As[icA + 0][irA] = av.x;
        As[icA + 1][irA] = av.y;
        As[icA + 2][irA] = av.z;
        As[icA + 3][irA] = av.w;
        *reinterpret_cast<float4*>(&Bs[irB][icB]) =
            *reinterpret_cast<const float4*>(Bptr + (size_t)k0 * N);
        __syncthreads();
        #pragma unroll
        for (int k = 0; k < 8; k++) {
            float4 m0 = *reinterpret_cast<const float4*>(&As[k][trow * 8]);
            float4 m1 = *reinterpret_cast<const float4*>(&As[k][trow * 8 + 4]);
            float4 n0 = *reinterpret_cast<const float4*>(&Bs[k][tcol * 8]);
            float4 n1 = *reinterpret_cast<const float4*>(&Bs[k][tcol * 8 + 4]);
            float rm[8] = {m0.x, m0.y, m0.z, m0.w, m1.x, m1.y, m1.z, m1.w};
            float rn[8] = {n0.x, n0.y, n0.z, n0.w, n1.x, n1.y, n1.z, n1.w};
            #pragma unroll
            for (int m = 0; m < 8; m++)
                #pragma unroll
                for (int n = 0; n < 8; n++)
                    acc[m][n] += rm[m] * rn[n];
        }
        __syncthreads();
    }

    float* Cbase = (c_mode == 0) ? g_Q : (c_mode == 1 ? g_KV : Cp);
    const int col0 = bcol * 128 + tcol * 8;
    #pragma unroll
    for (int m = 0; m < 8; m++) {
        int row = brow * 128 + trow * 8 + m;
        float* Crow;
        if (c_mode == 2) {
            int b = row >> 12, t = row & 4095;
            Crow = Cbase + ((size_t)b * 4097 + t + 1) * N;
        } else {
            Crow = Cbase + (size_t)row * N;
        }
        #pragma unroll
        for (int n = 0; n < 8; n += 4) {
            float4 v;
            v.x = alpha * acc[m][n + 0];
            v.y = alpha * acc[m][n + 1];
            v.z = alpha * acc[m][n + 2];
            v.w = alpha * acc[m][n + 3];
            if (bias) {
                v.x += bias[col0 + n + 0];
                v.y += bias[col0 + n + 1];
                v.z += bias[col0 + n + 2];
                v.w += bias[col0 + n + 3];
            }
            *reinterpret_cast<float4*>(Crow + col0 + n) = v;
        }
    }
}

// ---------------- sim + softmax per (b, h, chunk) ----------------
// smem: qs[64][64] + ks transposed [64][132]  => 50176 bytes dynamic
__global__ __launch_bounds__(256)
void attn_kernel(const float* __restrict__ nullk)
{
    extern __shared__ float sm[];
    float* qs = sm;              // [i][d]   4096 floats
    float* ks = sm + 64 * 64;    // [d][j] padded 132: ks[d*132 + j]
    const int tid = threadIdx.x;
    const int n = blockIdx.x & 63;
    const int h = (blockIdx.x >> 6) & 7;
    const int b = blockIdx.x >> 9;

    const float* qsrc = g_Q + ((size_t)(b * SROWS + n * 64)) * DINNER + h * 64;
    for (int t = tid; t < 1024; t += 256) {
        int i = t >> 4, d4 = (t & 15) << 2;
        float4 v = *reinterpret_cast<const float4*>(qsrc + (size_t)i * DINNER + d4);
        qs[i * 64 + d4 + 0] = v.x;
        qs[i * 64 + d4 + 1] = v.y;
        qs[i * 64 + d4 + 2] = v.z;
        qs[i * 64 + d4 + 3] = v.w;
    }
    if (tid < 64) ks[tid * 132 + 0] = nullk[h * 64 + tid];   // null key at j=0
    const float* ksrc = g_KV + (size_t)(b * CROWS + n * 128) * 1024 + h * 64;
    for (int e = tid; e < 128 * 64; e += 256) {
        int j = e >> 6, d = e & 63;
        ks[d * 132 + j + 1] = ksrc[(size_t)j * 1024 + d];
    }
    __syncthreads();

    const int warp = tid >> 5, lane = tid & 31;
    #pragma unroll
    for (int grp = 0; grp < 2; grp++) {
        const int i0 = warp * 8 + grp * 4;
        float acc[4][5] = {};
        #pragma unroll 4
        for (int d = 0; d < 64; d++) {
            float kv[5];
            #pragma unroll
            for (int jj = 0; jj < 5; jj++) {
                int j = lane + jj * 32;
                kv[jj] = (j < JDIM) ? ks[d * 132 + j] : 0.f;
            }
            #pragma unroll
            for (int r = 0; r < 4; r++) {
                float qv = qs[(i0 + r) * 64 + d];
                #pragma unroll
                for (int jj = 0; jj < 5; jj++) acc[r][jj] += qv * kv[jj];
            }
        }
        #pragma unroll
        for (int r = 0; r < 4; r++) {
            float mx = -1e30f;
            #pragma unroll
            for (int jj = 0; jj < 5; jj++)
                if (lane + jj * 32 < JDIM) mx = fmaxf(mx, acc[r][jj]);
            #pragma unroll
            for (int o = 16; o > 0; o >>= 1)
                mx = fmaxf(mx, __shfl_xor_sync(0xffffffffu, mx, o));
            float e5[5], s = 0.f;
            #pragma unroll
            for (int jj = 0; jj < 5; jj++) {
                if (lane + jj * 32 < JDIM) { e5[jj] = __expf(acc[r][jj] - mx); s += e5[jj]; }
                else e5[jj] = 0.f;
            }
            #pragma unroll
            for (int o = 16; o > 0; o >>= 1)
                s += __shfl_xor_sync(0xffffffffu, s, o);
            float inv = 1.f / s;
            float* prow = g_P + ((((size_t)(b * NH + h) * NCH + n) * 64) + (i0 + r)) * JDIM;
            #pragma unroll
            for (int jj = 0; jj < 5; jj++) {
                int j = lane + jj * 32;
                if (j < JDIM) prow[j] = e5[jj] * inv;
            }
        }
    }
}

// ---------------- 8x8 head mix: Pm[g] = sum_h Wth[g,h] P[h] + bth[g] ----------------
__global__ __launch_bounds__(256)
void mix_kernel(const float* __restrict__ Wth, const float* __restrict__ bth)
{
    __shared__ float w[64];
    __shared__ float bt[8];
    if (threadIdx.x < 64) w[threadIdx.x] = Wth[threadIdx.x];
    if (threadIdx.x < 8)  bt[threadIdx.x] = bth[threadIdx.x];
    __syncthreads();
    const size_t inner = (size_t)NCH * 64 * JDIM;   // per (b,h)
    const size_t total = (size_t)BATCH * inner;
    for (size_t idx = (size_t)blockIdx.x * blockDim.x + threadIdx.x;
         idx < total; idx += (size_t)gridDim.x * blockDim.x) {
        size_t b = idx / inner, r = idx - b * inner;
        const float* pb = g_P + (b * NH) * inner + r;
        float p[8];
        #pragma unroll
        for (int hh = 0; hh < 8; hh++) p[hh] = pb[hh * inner];
        float* ob = g_Pm + (b * NH) * inner + r;
        #pragma unroll
        for (int gg = 0; gg < 8; gg++) {
            float a = bt[gg];
            #pragma unroll
            for (int hh = 0; hh < 8; hh++) a += w[gg * 8 + hh] * p[hh];
            ob[gg * inner] = a;
        }
    }
}

// ---------------- PV: O[b,n,i, g*64+d] = sum_j Pm[b,g,n,i,j] * V[g][j][d] ----------------
// smem: pm[64*129] + vs[129*64]  => 66048 bytes dynamic
__global__ __launch_bounds__(256)
void pv_kernel(const float* __restrict__ nullv)
{
    extern __shared__ float sm[];
    float* pm = sm;                 // [i][j]
    float* vs = sm + 64 * JDIM;     // [j][d]
    const int tid = threadIdx.x;
    const int n = blockIdx.x & 63;
    const int g = (blockIdx.x >> 6) & 7;
    const int b = blockIdx.x >> 9;

    const float* psrc = g_Pm + (((size_t)(b * NH + g) * NCH + n)) * 64 * JDIM;
    for (int t = tid; t < (64 * JDIM) / 4; t += 256)
        reinterpret_cast<float4*>(pm)[t] = reinterpret_cast<const float4*>(psrc)[t];
    if (tid < 16)
        reinterpret_cast<float4*>(vs)[tid] =
            reinterpret_cast<const float4*>(nullv + g * 64)[tid];  // null value at j=0
    const float* vsrc = g_KV + (size_t)(b * CROWS + n * 128) * 1024 + 512 + g * 64;
    for (int e = tid; e < 128 * 16; e += 256) {
        int j = e >> 4, d4 = (e & 15) << 2;
        float4 v = *reinterpret_cast<const float4*>(vsrc + (size_t)j * 1024 + d4);
        *reinterpret_cast<float4*>(vs + (j + 1) * 64 + d4) = v;
    }
    __syncthreads();

    const int i = tid >> 2;
    const int dbase = (tid & 3) << 4;
    float acc[16] = {};
    for (int j = 0; j < JDIM; j++) {
        float p = pm[i * JDIM + j];
        #pragma unroll
        for (int dd = 0; dd < 16; dd++)
            acc[dd] += p * vs[j * 64 + dbase + dd];
    }
    float* orow = g_O + ((size_t)(b * SROWS + n * 64 + i)) * DINNER + g * 64 + dbase;
    #pragma unroll
    for (int dd = 0; dd < 16; dd += 4)
        *reinterpret_cast<float4*>(orow + dd) =
            make_float4(acc[dd], acc[dd + 1], acc[dd + 2], acc[dd + 3]);
}

// ---------------- zero out t=0 row per batch ----------------
__global__ void zero_row0_kernel(float* __restrict__ out)
{
    int idx = blockIdx.x * blockDim.x + threadIdx.x;
    if (idx < BATCH * DMODEL) {
        int b = idx >> 10, d = idx & 1023;
        out[(size_t)b * 4097 * DMODEL + d] = 0.f;
    }
}

// ---------------- launch ----------------
extern "C" void kernel_launch(void* const* d_in, const int* in_sizes, int n_in,
                              void* d_out, int out_size)
{
    const float* seq   = (const float*)d_in[0];
    const float* ctx   = (const float*)d_in[1];
    const float* Wq    = (const float*)d_in[2];
    const float* Wkv   = (const float*)d_in[3];
    const float* Wout  = (const float*)d_in[4];
    const float* b_out = (const float*)d_in[5];
    const float* nullk = (const float*)d_in[6];
    const float* nullv = (const float*)d_in[7];
    const float* Wth   = (const float*)d_in[8];
    const float* bth   = (const float*)d_in[9];
    float* out = (float*)d_out;

    cudaFuncSetAttribute(attn_kernel, cudaFuncAttributeMaxDynamicSharedMemorySize, 50176);
    cudaFuncSetAttribute(pv_kernel,   cudaFuncAttributeMaxDynamicSharedMemorySize, 66048);

    // Q = (seq[:,1:] @ Wq) * DIM_HEAD^-0.5
    sgemm_kernel<<<dim3(4, 128), 256>>>(seq, Wq, nullptr,
                                        16384, 512, 1024, 0.125f, nullptr, 1, 0);
    // KV = pad(context) @ Wkv
    sgemm_kernel<<<dim3(8, 256), 256>>>(ctx, Wkv, nullptr,
                                        32768, 1024, 1024, 1.0f, nullptr, 2, 1);
    // softmax(q k^T) per (b, h, chunk)
    attn_kernel<<<BATCH * NH * NCH, 256, 50176>>>(nullk);
    // head mixing
    mix_kernel<<<4096, 256>>>(Wth, bth);
    // attention output
    pv_kernel<<<BATCH * NH * NCH, 256, 66048>>>(nullv);
    // out = O @ Wout + b_out, scattered to d_out rows t=1..4096
    sgemm_kernel<<<dim3(8, 128), 256>>>(nullptr, Wout, out,
                                        16384, 1024, 512, 1.0f, b_out, 3, 2);
    // t = 0 rows are zero padding
    zero_row0_kernel<<<4, 1024>>>(out);
}

// round 4
// speedup vs baseline: 2.1115x; 2.1115x over previous
#include <cuda_runtime.h>
#include <cuda_bf16.h>
#include <cstdint>
#include <math.h>

// ---------------- problem constants ----------------
#define BATCH  4
#define NH     8
#define NCH    64
#define SROWS  4096
#define CROWS  8192
#define DMODEL 1024
#define DINNER 512
#define JDIM   129

// ---------------- scratch (device globals; no allocation) ----------------
__device__ float g_Q [(size_t)BATCH * SROWS * DINNER];
__device__ float g_KV[(size_t)BATCH * CROWS * 1024];
__device__ float g_P [(size_t)BATCH * NH * NCH * 64 * JDIM];
__device__ float g_Pm[(size_t)BATCH * NH * NCH * 64 * JDIM];

// pre-split activations (hi/lo bf16)
__device__ __nv_bfloat16 g_Sh[(size_t)16384 * 1024];   // seq rows remapped
__device__ __nv_bfloat16 g_Sl[(size_t)16384 * 1024];
__device__ __nv_bfloat16 g_Ch[(size_t)32768 * 1024];   // ctx rows padded
__device__ __nv_bfloat16 g_Cl[(size_t)32768 * 1024];
__device__ __nv_bfloat16 g_Oh[(size_t)16384 * 512];    // attention out
__device__ __nv_bfloat16 g_Ol[(size_t)16384 * 512];

// pre-split weights, bf16 hi/lo, transposed to [N][K]
__device__ __nv_bfloat16 g_Wq_hi [1024 * 512];
__device__ __nv_bfloat16 g_Wq_lo [1024 * 512];
__device__ __nv_bfloat16 g_Wkv_hi[1024 * 1024];
__device__ __nv_bfloat16 g_Wkv_lo[1024 * 1024];
__device__ __nv_bfloat16 g_Wo_hi [512 * 1024];
__device__ __nv_bfloat16 g_Wo_lo [512 * 1024];

// ---------------- asm helpers (all sm_80-level, no arch-specific ops) ----------------
__device__ __forceinline__ uint32_t smem_u32(const void* p) {
    uint32_t a;
    asm("{ .reg .u64 t; cvta.to.shared.u64 t, %1; cvt.u32.u64 %0, t; }" : "=r"(a) : "l"(p));
    return a;
}
#define CP_ASYNC16(dst, src) \
    asm volatile("cp.async.cg.shared.global [%0], [%1], 16;" :: "r"(dst), "l"(src))
#define CP_COMMIT() asm volatile("cp.async.commit_group;" ::: "memory")
#define CP_WAIT(n)  asm volatile("cp.async.wait_group %0;" :: "n"(n) : "memory")

#define LDSM_X4(r, addr) \
    asm volatile("ldmatrix.sync.aligned.m8n8.x4.shared.b16 {%0,%1,%2,%3}, [%4];" \
        : "=r"((r)[0]), "=r"((r)[1]), "=r"((r)[2]), "=r"((r)[3]) : "r"(addr))

__device__ __forceinline__ void mma_bf16(float* c, const uint32_t* a, uint32_t b0, uint32_t b1) {
    asm volatile("mma.sync.aligned.m16n8k16.row.col.f32.bf16.bf16.f32 "
                 "{%0,%1,%2,%3}, {%4,%5,%6,%7}, {%8,%9}, {%0,%1,%2,%3};"
                 : "+f"(c[0]), "+f"(c[1]), "+f"(c[2]), "+f"(c[3])
                 : "r"(a[0]), "r"(a[1]), "r"(a[2]), "r"(a[3]), "r"(b0), "r"(b1));
}

// ---------------- weight split: W[K,N] fp32 -> Whi/Wlo[N,K] bf16 ----------------
__global__ void split_w_kernel(const float* __restrict__ W,
                               __nv_bfloat16* __restrict__ Whi,
                               __nv_bfloat16* __restrict__ Wlo, int K, int N)
{
    __shared__ float t[32][33];
    int kb = blockIdx.x * 32, nb = blockIdx.y * 32;
    int x = threadIdx.x, y = threadIdx.y;
    for (int i = y; i < 32; i += 8)
        t[i][x] = W[(size_t)(kb + i) * N + nb + x];
    __syncthreads();
    for (int i = y; i < 32; i += 8) {
        float w = t[x][i];
        __nv_bfloat16 h = __float2bfloat16(w);
        __nv_bfloat16 l = __float2bfloat16(w - __bfloat162float(h));
        size_t o = (size_t)(nb + i) * K + kb + x;
        Whi[o] = h; Wlo[o] = l;
    }
}

// ---------------- activation split: fp32 rows -> hi/lo bf16 [M][1024] ----------------
// mode 1: seq remap (row -> seq[b, t+1]); mode 2: ctx pad (first 127 rows zero)
__global__ __launch_bounds__(256)
void split_act_kernel(const float* __restrict__ src,
                      __nv_bfloat16* __restrict__ Dh,
                      __nv_bfloat16* __restrict__ Dl, int mode)
{
    size_t idx = (size_t)blockIdx.x * 256 + threadIdx.x;  // float4 index, K=1024 -> 256 per row
    int row = (int)(idx >> 8), f4 = (int)(idx & 255);
    const float* p;
    if (mode == 1) { int b = row >> 12, t = row & 4095; p = src + ((size_t)b * 4097 + t + 1) * 1024; }
    else           { int b = row >> 13, r = row & 8191;
                     p = (r < 127) ? nullptr : src + ((size_t)b * 8065 + (r - 127)) * 1024; }
    float4 v = p ? *reinterpret_cast<const float4*>(p + f4 * 4) : make_float4(0.f, 0.f, 0.f, 0.f);
    __nv_bfloat16 hx = __float2bfloat16(v.x), hy = __float2bfloat16(v.y);
    __nv_bfloat16 hz = __float2bfloat16(v.z), hw = __float2bfloat16(v.w);
    __nv_bfloat16 lx = __float2bfloat16(v.x - __bfloat162float(hx));
    __nv_bfloat16 ly = __float2bfloat16(v.y - __bfloat162float(hy));
    __nv_bfloat16 lz = __float2bfloat16(v.z - __bfloat162float(hz));
    __nv_bfloat16 lw = __float2bfloat16(v.w - __bfloat162float(hw));
    size_t o = (size_t)row * 1024 + f4 * 4;
    *reinterpret_cast<__nv_bfloat162*>(Dh + o)     = __halves2bfloat162(hx, hy);
    *reinterpret_cast<__nv_bfloat162*>(Dh + o + 2) = __halves2bfloat162(hz, hw);
    *reinterpret_cast<__nv_bfloat162*>(Dl + o)     = __halves2bfloat162(lx, ly);
    *reinterpret_cast<__nv_bfloat162*>(Dl + o + 2) = __halves2bfloat162(lz, lw);
}

// ---------------- bf16x3 mma.sync GEMM ----------------
// C[M,N] = A[M,K] * B[N,K]^T (both A,B given as hi/lo bf16, K-contiguous)
// CTA tile 128x128, BK=32, 3-stage cp.async pipeline, 8 warps (64x32 each).
// smem stage (32KB): A region 16KB then B region 16KB; row = 128B packing
// [hi k0..31 | lo k0..31] with 16B-chunk XOR-8 swizzle.
// c_mode 0: plain C; 2: scatter rows to d_out (b*4097 + t + 1)
#define GSTG 32768
#define GEMM_SMEM (3 * GSTG)

__global__ __launch_bounds__(256, 1)
void mma_gemm_kernel(const __nv_bfloat16* __restrict__ Ah, const __nv_bfloat16* __restrict__ Al,
                     const __nv_bfloat16* __restrict__ Bh, const __nv_bfloat16* __restrict__ Bl,
                     float* __restrict__ C, int M, int N, int K,
                     float alpha, const float* __restrict__ bias, int c_mode)
{
    extern __shared__ char smem[];
    const uint32_t sbase = smem_u32(smem);
    const int tid = threadIdx.x, warp = tid >> 5, lane = tid & 31;
    const int bn = blockIdx.x, bm = blockIdx.y;
    const int warp_m = warp >> 2, warp_n = warp & 3;
    const int KT = K >> 5;

    // cp.async mapping: 2048 16B chunks per stage, 8 per thread
    int ld_row[8], ld_ch[8];
    const __nv_bfloat16* ld_src[8];
    uint32_t ld_dst[8];
    #pragma unroll
    for (int c = 0; c < 8; c++) {
        int idx = (c << 8) + tid;           // 0..2047
        int isB = idx >> 10;
        int id = idx & 1023;
        int row = id >> 3, ch = id & 7;
        ld_row[c] = row; ld_ch[c] = ch;
        const __nv_bfloat16* base;
        if (!isB) base = ((ch < 4) ? Ah : Al) + (size_t)(bm * 128 + row) * K + (ch & 3) * 8;
        else      base = ((ch < 4) ? Bh : Bl) + (size_t)(bn * 128 + row) * K + (ch & 3) * 8;
        ld_src[c] = base;
        ld_dst[c] = sbase + (isB ? 16384 : 0) + row * 128 + ((ch ^ (row & 7)) << 4);
    }

    auto issue_stage = [&](int kt, int s) {
        #pragma unroll
        for (int c = 0; c < 8; c++)
            CP_ASYNC16(ld_dst[c] + s * GSTG, ld_src[c] + kt * 32);
    };

    float acc[4][4][4] = {};

    // ldmatrix per-lane row/k-half decomposition
    const int rlaneA = (lane & 7) + (((lane >> 3) & 1) << 3);
    const int khalfA = (lane >> 4) & 1;
    const int rlaneB = (lane & 7) + (((lane >> 4) & 1) << 3);
    const int khalfB = (lane >> 3) & 1;

    // prologue: stages 0,1
    issue_stage(0, 0); CP_COMMIT();
    if (KT > 1) issue_stage(1, 1);
    CP_COMMIT();

    for (int kt = 0; kt < KT; kt++) {
        const int s = kt % 3;
        CP_WAIT(1);
        __syncthreads();
        // prefetch stage kt+2
        if (kt + 2 < KT) issue_stage(kt + 2, (kt + 2) % 3);
        CP_COMMIT();

        const uint32_t sA = sbase + s * GSTG;
        const uint32_t sB = sA + 16384;
        #pragma unroll
        for (int kk = 0; kk < 2; kk++) {
            uint32_t aH[4][4], aL[4][4], bH[2][4], bL[2][4];
            #pragma unroll
            for (int mf = 0; mf < 4; mf++) {
                int r = warp_m * 64 + mf * 16 + rlaneA;
                int ch = kk * 2 + khalfA;
                LDSM_X4(aH[mf], sA + r * 128 + (((ch)     ^ (r & 7)) << 4));
                LDSM_X4(aL[mf], sA + r * 128 + (((ch + 4) ^ (r & 7)) << 4));
            }
            #pragma unroll
            for (int p = 0; p < 2; p++) {
                int r = warp_n * 32 + p * 16 + rlaneB;
                int ch = kk * 2 + khalfB;
                LDSM_X4(bH[p], sB + r * 128 + (((ch)     ^ (r & 7)) << 4));
                LDSM_X4(bL[p], sB + r * 128 + (((ch + 4) ^ (r & 7)) << 4));
            }
            #pragma unroll
            for (int mf = 0; mf < 4; mf++)
                #pragma unroll
                for (int nf = 0; nf < 4; nf++) {
                    uint32_t b0h = bH[nf >> 1][(nf & 1) * 2], b1h = bH[nf >> 1][(nf & 1) * 2 + 1];
                    uint32_t b0l = bL[nf >> 1][(nf & 1) * 2], b1l = bL[nf >> 1][(nf & 1) * 2 + 1];
                    mma_bf16(acc[mf][nf], aH[mf], b0h, b1h);   // ah*bh
                    mma_bf16(acc[mf][nf], aH[mf], b0l, b1l);   // ah*bl
                    mma_bf16(acc[mf][nf], aL[mf], b0h, b1h);   // al*bh
                }
        }
        __syncthreads();
    }

    // epilogue
    const int row_in = lane >> 2;
    const int col_in = (lane & 3) * 2;
    #pragma unroll
    for (int mf = 0; mf < 4; mf++) {
        int r0 = bm * 128 + warp_m * 64 + mf * 16 + row_in;
        float *p0, *p1;
        if (c_mode == 2) {
            int b0 = r0 >> 12, t0 = r0 & 4095;
            int r1 = r0 + 8, b1 = r1 >> 12, t1 = r1 & 4095;
            p0 = C + ((size_t)b0 * 4097 + t0 + 1) * N;
            p1 = C + ((size_t)b1 * 4097 + t1 + 1) * N;
        } else {
            p0 = C + (size_t)r0 * N;
            p1 = p0 + (size_t)8 * N;
        }
        #pragma unroll
        for (int nf = 0; nf < 4; nf++) {
            int c0 = bn * 128 + warp_n * 32 + nf * 8 + col_in;
            float bx = 0.f, by = 0.f;
            if (bias) { float2 bv = *reinterpret_cast<const float2*>(bias + c0); bx = bv.x; by = bv.y; }
            float2 v0, v1;
            v0.x = alpha * acc[mf][nf][0] + bx; v0.y = alpha * acc[mf][nf][1] + by;
            v1.x = alpha * acc[mf][nf][2] + bx; v1.y = alpha * acc[mf][nf][3] + by;
            *reinterpret_cast<float2*>(p0 + c0) = v0;
            *reinterpret_cast<float2*>(p1 + c0) = v1;
        }
    }
}

// ---------------- sim + softmax per (b, h, chunk) ----------------
__global__ __launch_bounds__(256)
void attn_kernel(const float* __restrict__ nullk)
{
    extern __shared__ float sm[];
    float* qs = sm;
    float* ks = sm + 64 * 64;
    const int tid = threadIdx.x;
    const int n = blockIdx.x & 63;
    const int h = (blockIdx.x >> 6) & 7;
    const int b = blockIdx.x >> 9;

    const float* qsrc = g_Q + ((size_t)(b * SROWS + n * 64)) * DINNER + h * 64;
    for (int t = tid; t < 1024; t += 256) {
        int i = t >> 4, d4 = (t & 15) << 2;
        float4 v = *reinterpret_cast<const float4*>(qsrc + (size_t)i * DINNER + d4);
        qs[i * 64 + d4 + 0] = v.x;
        qs[i * 64 + d4 + 1] = v.y;
        qs[i * 64 + d4 + 2] = v.z;
        qs[i * 64 + d4 + 3] = v.w;
    }
    if (tid < 64) ks[tid * 132 + 0] = nullk[h * 64 + tid];
    const float* ksrc = g_KV + (size_t)(b * CROWS + n * 128) * 1024 + h * 64;
    for (int e = tid; e < 128 * 64; e += 256) {
        int j = e >> 6, d = e & 63;
        ks[d * 132 + j + 1] = ksrc[(size_t)j * 1024 + d];
    }
    __syncthreads();

    const int warp = tid >> 5, lane = tid & 31;
    #pragma unroll
    for (int grp = 0; grp < 2; grp++) {
        const int i0 = warp * 8 + grp * 4;
        float acc[4][5] = {};
        #pragma unroll 4
        for (int d = 0; d < 64; d++) {
            float kv[5];
            #pragma unroll
            for (int jj = 0; jj < 5; jj++) {
                int j = lane + jj * 32;
                kv[jj] = (j < JDIM) ? ks[d * 132 + j] : 0.f;
            }
            #pragma unroll
            for (int r = 0; r < 4; r++) {
                float qv = qs[(i0 + r) * 64 + d];
                #pragma unroll
                for (int jj = 0; jj < 5; jj++) acc[r][jj] += qv * kv[jj];
            }
        }
        #pragma unroll
        for (int r = 0; r < 4; r++) {
            float mx = -1e30f;
            #pragma unroll
            for (int jj = 0; jj < 5; jj++)
                if (lane + jj * 32 < JDIM) mx = fmaxf(mx, acc[r][jj]);
            #pragma unroll
            for (int o = 16; o > 0; o >>= 1)
                mx = fmaxf(mx, __shfl_xor_sync(0xffffffffu, mx, o));
            float e5[5], ssum = 0.f;
            #pragma unroll
            for (int jj = 0; jj < 5; jj++) {
                if (lane + jj * 32 < JDIM) { e5[jj] = __expf(acc[r][jj] - mx); ssum += e5[jj]; }
                else e5[jj] = 0.f;
            }
            #pragma unroll
            for (int o = 16; o > 0; o >>= 1)
                ssum += __shfl_xor_sync(0xffffffffu, ssum, o);
            float inv = 1.f / ssum;
            float* prow = g_P + ((((size_t)(b * NH + h) * NCH + n) * 64) + (i0 + r)) * JDIM;
            #pragma unroll
            for (int jj = 0; jj < 5; jj++) {
                int j = lane + jj * 32;
                if (j < JDIM) prow[j] = e5[jj] * inv;
            }
        }
    }
}

// ---------------- 8x8 head mix ----------------
__global__ __launch_bounds__(256)
void mix_kernel(const float* __restrict__ Wth, const float* __restrict__ bth)
{
    __shared__ float w[64];
    __shared__ float bt[8];
    if (threadIdx.x < 64) w[threadIdx.x] = Wth[threadIdx.x];
    if (threadIdx.x < 8)  bt[threadIdx.x] = bth[threadIdx.x];
    __syncthreads();
    const size_t inner = (size_t)NCH * 64 * JDIM;
    const size_t total = (size_t)BATCH * inner;
    for (size_t idx = (size_t)blockIdx.x * blockDim.x + threadIdx.x;
         idx < total; idx += (size_t)gridDim.x * blockDim.x) {
        size_t b = idx / inner, r = idx - b * inner;
        const float* pb = g_P + (b * NH) * inner + r;
        float p[8];
        #pragma unroll
        for (int hh = 0; hh < 8; hh++) p[hh] = pb[hh * inner];
        float* ob = g_Pm + (b * NH) * inner + r;
        #pragma unroll
        for (int gg = 0; gg < 8; gg++) {
            float a = bt[gg];
            #pragma unroll
            for (int hh = 0; hh < 8; hh++) a += w[gg * 8 + hh] * p[hh];
            ob[gg * inner] = a;
        }
    }
}

// ---------------- PV (writes hi/lo bf16 directly) ----------------
__global__ __launch_bounds__(256)
void pv_kernel(const float* __restrict__ nullv)
{
    extern __shared__ float sm[];
    float* pm = sm;
    float* vs = sm + 64 * JDIM;
    const int tid = threadIdx.x;
    const int n = blockIdx.x & 63;
    const int g = (blockIdx.x >> 6) & 7;
    const int b = blockIdx.x >> 9;

    const float* psrc = g_Pm + (((size_t)(b * NH + g) * NCH + n)) * 64 * JDIM;
    for (int t = tid; t < (64 * JDIM) / 4; t += 256)
        reinterpret_cast<float4*>(pm)[t] = reinterpret_cast<const float4*>(psrc)[t];
    if (tid < 16)
        reinterpret_cast<float4*>(vs)[tid] =
            reinterpret_cast<const float4*>(nullv + g * 64)[tid];
    const float* vsrc = g_KV + (size_t)(b * CROWS + n * 128) * 1024 + 512 + g * 64;
    for (int e = tid; e < 128 * 16; e += 256) {
        int j = e >> 4, d4 = (e & 15) << 2;
        float4 v = *reinterpret_cast<const float4*>(vsrc + (size_t)j * 1024 + d4);
        *reinterpret_cast<float4*>(vs + (j + 1) * 64 + d4) = v;
    }
    __syncthreads();

    const int i = tid >> 2;
    const int dbase = (tid & 3) << 4;
    float acc[16] = {};
    for (int j = 0; j < JDIM; j++) {
        float p = pm[i * JDIM + j];
        #pragma unroll
        for (int dd = 0; dd < 16; dd++)
            acc[dd] += p * vs[j * 64 + dbase + dd];
    }
    size_t o = ((size_t)(b * SROWS + n * 64 + i)) * DINNER + g * 64 + dbase;
    #pragma unroll
    for (int dd = 0; dd < 16; dd += 2) {
        __nv_bfloat16 h0 = __float2bfloat16(acc[dd]);
        __nv_bfloat16 h1 = __float2bfloat16(acc[dd + 1]);
        __nv_bfloat16 l0 = __float2bfloat16(acc[dd] - __bfloat162float(h0));
        __nv_bfloat16 l1 = __float2bfloat16(acc[dd + 1] - __bfloat162float(h1));
        *reinterpret_cast<__nv_bfloat162*>(g_Oh + o + dd) = __halves2bfloat162(h0, h1);
        *reinterpret_cast<__nv_bfloat162*>(g_Ol + o + dd) = __halves2bfloat162(l0, l1);
    }
}

// ---------------- zero out t=0 row ----------------
__global__ void zero_row0_kernel(float* __restrict__ out)
{
    int idx = blockIdx.x * blockDim.x + threadIdx.x;
    if (idx < BATCH * DMODEL) {
        int b = idx >> 10, d = idx & 1023;
        out[(size_t)b * 4097 * DMODEL + d] = 0.f;
    }
}

// ---------------- launch ----------------
extern "C" void kernel_launch(void* const* d_in, const int* in_sizes, int n_in,
                              void* d_out, int out_size)
{
    const float* seq   = (const float*)d_in[0];
    const float* ctx   = (const float*)d_in[1];
    const float* Wq    = (const float*)d_in[2];
    const float* Wkv   = (const float*)d_in[3];
    const float* Wout  = (const float*)d_in[4];
    const float* b_out = (const float*)d_in[5];
    const float* nullk = (const float*)d_in[6];
    const float* nullv = (const float*)d_in[7];
    const float* Wth   = (const float*)d_in[8];
    const float* bth   = (const float*)d_in[9];
    float* out = (float*)d_out;

    cudaFuncSetAttribute(mma_gemm_kernel, cudaFuncAttributeMaxDynamicSharedMemorySize, GEMM_SMEM);
    cudaFuncSetAttribute(attn_kernel, cudaFuncAttributeMaxDynamicSharedMemorySize, 50176);
    cudaFuncSetAttribute(pv_kernel,   cudaFuncAttributeMaxDynamicSharedMemorySize, 66048);

    __nv_bfloat16 *wq_hi, *wq_lo, *wkv_hi, *wkv_lo, *wo_hi, *wo_lo;
    __nv_bfloat16 *sh, *sl, *ch_, *cl, *oh, *ol;
    float *q32, *kv32;
    cudaGetSymbolAddress((void**)&wq_hi,  g_Wq_hi);
    cudaGetSymbolAddress((void**)&wq_lo,  g_Wq_lo);
    cudaGetSymbolAddress((void**)&wkv_hi, g_Wkv_hi);
    cudaGetSymbolAddress((void**)&wkv_lo, g_Wkv_lo);
    cudaGetSymbolAddress((void**)&wo_hi,  g_Wo_hi);
    cudaGetSymbolAddress((void**)&wo_lo,  g_Wo_lo);
    cudaGetSymbolAddress((void**)&sh,  g_Sh);
    cudaGetSymbolAddress((void**)&sl,  g_Sl);
    cudaGetSymbolAddress((void**)&ch_, g_Ch);
    cudaGetSymbolAddress((void**)&cl,  g_Cl);
    cudaGetSymbolAddress((void**)&oh,  g_Oh);
    cudaGetSymbolAddress((void**)&ol,  g_Ol);
    cudaGetSymbolAddress((void**)&q32,  g_Q);
    cudaGetSymbolAddress((void**)&kv32, g_KV);

    // weight splits [N][K]
    split_w_kernel<<<dim3(32, 16), dim3(32, 8)>>>(Wq,   wq_hi,  wq_lo,  1024, 512);
    split_w_kernel<<<dim3(32, 32), dim3(32, 8)>>>(Wkv,  wkv_hi, wkv_lo, 1024, 1024);
    split_w_kernel<<<dim3(16, 32), dim3(32, 8)>>>(Wout, wo_hi,  wo_lo,  512, 1024);

    // activation splits (with row remap / padding folded in)
    split_act_kernel<<<16384, 256>>>(seq, sh,  sl, 1);
    split_act_kernel<<<32768, 256>>>(ctx, ch_, cl, 2);

    // Q = (seq[:,1:] @ Wq) * 0.125
    mma_gemm_kernel<<<dim3(4, 128), 256, GEMM_SMEM>>>(sh, sl, wq_hi, wq_lo, q32,
                                                      16384, 512, 1024, 0.125f, nullptr, 0);
    // KV = pad(context) @ Wkv
    mma_gemm_kernel<<<dim3(8, 256), 256, GEMM_SMEM>>>(ch_, cl, wkv_hi, wkv_lo, kv32,
                                                      32768, 1024, 1024, 1.0f, nullptr, 0);
    attn_kernel<<<BATCH * NH * NCH, 256, 50176>>>(nullk);
    mix_kernel<<<4096, 256>>>(Wth, bth);
    pv_kernel<<<BATCH * NH * NCH, 256, 66048>>>(nullv);
    // out = O @ Wout + b_out, scattered to d_out rows t=1..4096
    mma_gemm_kernel<<<dim3(8, 128), 256, GEMM_SMEM>>>(oh, ol, wo_hi, wo_lo, out,
                                                      16384, 1024, 512, 1.0f, b_out, 2);
    zero_row0_kernel<<<4, 1024>>>(out);
}